// round 10
// baseline (speedup 1.0000x reference)
#include <cuda_runtime.h>
#include <cuda_fp16.h>
#include <math.h>
#include <stdint.h>

#define NBATCH 4
#define TSEQ   4096
#define DMODEL 1024
#define HSIZE  128
#define NROWS  (NBATCH * TSEQ)

__device__ __align__(16) __half g_q[(size_t)NROWS * HSIZE];
__device__ __align__(16) __half g_k[(size_t)NROWS * HSIZE];
__device__ __align__(16) __half g_v[(size_t)NROWS * HSIZE];

// ---------------------------------------------------------------------------
// Helpers
// ---------------------------------------------------------------------------
__device__ __forceinline__ uint32_t smem_u32(const void* p) {
    uint32_t a;
    asm("{ .reg .u64 t; cvta.to.shared.u64 t, %1; cvt.u32.u64 %0, t; }"
        : "=r"(a) : "l"(p));
    return a;
}

__device__ __forceinline__ uint32_t f2h2(float a, float b) {
    __half2 h = __floats2half2_rn(a, b);
    return *reinterpret_cast<uint32_t*>(&h);
}

__device__ __forceinline__ void mma16(float* c, const uint32_t* a, const uint32_t* b) {
    asm volatile(
        "mma.sync.aligned.m16n8k16.row.col.f32.f16.f16.f32 "
        "{%0,%1,%2,%3},{%4,%5,%6,%7},{%8,%9},{%0,%1,%2,%3};"
        : "+f"(c[0]), "+f"(c[1]), "+f"(c[2]), "+f"(c[3])
        : "r"(a[0]), "r"(a[1]), "r"(a[2]), "r"(a[3]), "r"(b[0]), "r"(b[1]));
}

__device__ __forceinline__ void ldm4(uint32_t* r, uint32_t a) {
    asm volatile("ldmatrix.sync.aligned.m8n8.x4.shared.b16 {%0,%1,%2,%3}, [%4];"
                 : "=r"(r[0]), "=r"(r[1]), "=r"(r[2]), "=r"(r[3]) : "r"(a));
}
__device__ __forceinline__ void ldm4t(uint32_t* r, uint32_t a) {
    asm volatile("ldmatrix.sync.aligned.m8n8.x4.trans.shared.b16 {%0,%1,%2,%3}, [%4];"
                 : "=r"(r[0]), "=r"(r[1]), "=r"(r[2]), "=r"(r[3]) : "r"(a));
}

#define CPA16(dst, src) \
    asm volatile("cp.async.cg.shared.global [%0], [%1], 16;" \
                 :: "r"(dst), "l"(src) : "memory")
#define CPA_COMMIT() asm volatile("cp.async.commit_group;" ::: "memory")
#define CPA_WAIT0()  asm volatile("cp.async.wait_group 0;" ::: "memory")

// ---------------------------------------------------------------------------
// Kernel 1: QKV projection, fp16 mma + ldmatrix, fp16 output.
// Wq pre-scaled by 1/sqrt(128).
// ---------------------------------------------------------------------------
#define QKV_PITCH_B 80
#define QKV_TILE_B  (128 * QKV_PITCH_B)
#define QKV_STAGE_B (2 * QKV_TILE_B)
#define QKV_SMEM    (2 * QKV_STAGE_B)

__global__ __launch_bounds__(256, 1) void qkv_kernel(
    const float* __restrict__ x,
    const float* __restrict__ Wq,
    const float* __restrict__ Wk,
    const float* __restrict__ Wv)
{
    extern __shared__ char sm1[];
    const uint32_t sbase = smem_u32(sm1);

    const int w  = blockIdx.x;
    const int rb = blockIdx.y;
    const float* __restrict__ W = (w == 0) ? Wq : ((w == 1) ? Wk : Wv);
    __half* out = (w == 0) ? g_q : ((w == 1) ? g_k : g_v);
    const float ws = (w == 0) ? 0.08838834764831845f : 1.0f;
    const int row0 = rb * 128;

    const int t = threadIdx.x;
    const int warp = t >> 5, lane = t & 31;
    const int g = lane >> 2, klo = lane & 3;
    const int l8 = lane & 7, qd = lane >> 3;
    const int m0 = (warp >> 2) * 64;
    const int n0 = (warp & 3) * 32;

    uint32_t arow[4], brow[2];
#pragma unroll
    for (int mf = 0; mf < 4; mf++)
        arow[mf] = (uint32_t)((m0 + mf * 16 + (qd & 1) * 8 + l8) * QKV_PITCH_B
                              + (qd >> 1) * 16);
#pragma unroll
    for (int p = 0; p < 2; p++)
        brow[p] = (uint32_t)((n0 + p * 16 + (qd >> 1) * 8 + l8) * QKV_PITCH_B
                             + (qd & 1) * 16);

    float C[4][4][4];
#pragma unroll
    for (int a = 0; a < 4; a++)
#pragma unroll
        for (int bb = 0; bb < 4; bb++)
#pragma unroll
            for (int cp = 0; cp < 4; cp++) C[a][bb][cp] = 0.f;

    float4 ra[4], rbv[4];
    const int lr = t >> 3, lc = (t & 7) * 4;

#define QKV_LOADG(kt)                                                          \
    {                                                                          \
        int k0_ = (kt) * 32;                                                   \
        _Pragma("unroll")                                                      \
        for (int i = 0; i < 4; i++) {                                          \
            int r = lr + i * 32;                                               \
            ra[i]  = *reinterpret_cast<const float4*>(                         \
                x + (size_t)(row0 + r) * DMODEL + k0_ + lc);                   \
            rbv[i] = *reinterpret_cast<const float4*>(                         \
                W + (size_t)r * DMODEL + k0_ + lc);                            \
        }                                                                      \
    }

#define QKV_STS(buf)                                                           \
    {                                                                          \
        char* A_ = sm1 + (buf) * QKV_STAGE_B;                                  \
        char* B_ = A_ + QKV_TILE_B;                                            \
        _Pragma("unroll")                                                      \
        for (int i = 0; i < 4; i++) {                                          \
            int r = lr + i * 32;                                               \
            uint32_t bo = (uint32_t)(r * QKV_PITCH_B + lc * 2);                \
            *reinterpret_cast<uint2*>(A_ + bo) =                               \
                make_uint2(f2h2(ra[i].x, ra[i].y), f2h2(ra[i].z, ra[i].w));    \
            *reinterpret_cast<uint2*>(B_ + bo) =                               \
                make_uint2(f2h2(rbv[i].x * ws, rbv[i].y * ws),                 \
                           f2h2(rbv[i].z * ws, rbv[i].w * ws));                \
        }                                                                      \
    }

    QKV_LOADG(0);
    QKV_STS(0);
    QKV_LOADG(1);
    __syncthreads();

    for (int kt = 0; kt < 32; kt++) {
        const int cur = kt & 1;
        if (kt + 1 < 32) QKV_STS(cur ^ 1);
        if (kt + 2 < 32) QKV_LOADG(kt + 2);

        const uint32_t Ab = sbase + cur * QKV_STAGE_B;
        const uint32_t Bb = Ab + QKV_TILE_B;
#pragma unroll
        for (int ks = 0; ks < 2; ks++) {
            uint32_t af[4][4], bf[2][4];
#pragma unroll
            for (int mf = 0; mf < 4; mf++) ldm4(af[mf], Ab + arow[mf] + ks * 32);
#pragma unroll
            for (int p = 0; p < 2; p++)    ldm4(bf[p], Bb + brow[p] + ks * 32);
#pragma unroll
            for (int mf = 0; mf < 4; mf++) {
                mma16(C[mf][0], af[mf], bf[0]);
                mma16(C[mf][1], af[mf], bf[0] + 2);
                mma16(C[mf][2], af[mf], bf[1]);
                mma16(C[mf][3], af[mf], bf[1] + 2);
            }
        }
        __syncthreads();
    }

#pragma unroll
    for (int mf = 0; mf < 4; mf++)
#pragma unroll
        for (int nf = 0; nf < 4; nf++) {
            int r  = row0 + m0 + mf * 16 + g;
            int cc = n0 + nf * 8 + 2 * klo;
            *reinterpret_cast<__half2*>(out + (size_t)r * HSIZE + cc) =
                __floats2half2_rn(C[mf][nf][0], C[mf][nf][1]);
            *reinterpret_cast<__half2*>(out + (size_t)(r + 8) * HSIZE + cc) =
                __floats2half2_rn(C[mf][nf][2], C[mf][nf][3]);
        }
}

// ---------------------------------------------------------------------------
// Kernel 2: causal flash attention, FA2 warp-owned-rows partition.
// 128 threads (4 warps), 64 q-rows/CTA (16 per warp), 64-key KV tiles.
// Softmax warp-local; P repacked from S accumulators in registers (no smem);
// 1 barrier per tile.  SMEM: K[2]|V[2] 16KB tiles = 64KB -> 3 CTAs/SM.
// Q staged through K-buf-1 then held as register fragments.
// Swizzle: 16B chunk ch stored at ch ^ (row & 7); row pitch 256 B.
// ---------------------------------------------------------------------------
#define ATT_KOFF  0
#define ATT_VOFF  32768
#define ATT_SMEM  65536

__global__ __launch_bounds__(128, 3) void attn_kernel(float* __restrict__ out)
{
    extern __shared__ __align__(16) char smc[];
    const uint32_t sb = smem_u32(smc);

    // bid -> (batch, qt): pairs (bid, 403-bid) are complementary in work.
    const int bid = blockIdx.x;
    const int rnk = (bid < 148) ? bid : 403 - bid;
    const int b   = rnk & 3;
    const int qt  = 63 - (rnk >> 2);
    const int q0  = qt * 64;

    const __half* qb = g_q + ((size_t)b * TSEQ + q0) * HSIZE;
    const __half* kb = g_k + (size_t)b * TSEQ * HSIZE;
    const __half* vb = g_v + (size_t)b * TSEQ * HSIZE;

    const int t = threadIdx.x, warp = t >> 5, lane = t & 31;
    const int g = lane >> 2, klo = lane & 3;
    const int l8 = lane & 7, qd = lane >> 3;

    // Stage Q into K-buf-1; K0/V0 into buf 0.  8 chunks per thread per array.
#pragma unroll
    for (int i = 0; i < 8; i++) {
        int lin = t + i * 128; int row = lin >> 4, ch = lin & 15;
        uint32_t dsw = (uint32_t)(row * 256 + ((ch ^ (row & 7)) << 4));
        CPA16(sb + ATT_KOFF + 16384 + dsw, qb + row * 128 + ch * 8);
        CPA16(sb + ATT_KOFF + dsw,         kb + row * 128 + ch * 8);
        CPA16(sb + ATT_VOFF + dsw,         vb + row * 128 + ch * 8);
    }
    CPA_COMMIT();
    CPA_WAIT0();
    __syncthreads();

    // Hoist Q fragments to registers: warp owns rows warp*16..+15, K=128.
    uint32_t Qf[8][4];
    {
        const int rq = warp * 16 + (qd & 1) * 8 + l8;
        const int cqa = qd >> 1;
        const uint32_t Qb = sb + ATT_KOFF + 16384;
#pragma unroll
        for (int ks = 0; ks < 8; ks++)
            ldm4(Qf[ks], Qb + rq * 256 + (((2 * ks + cqa) ^ l8) << 4));
    }
    __syncthreads();   // K-buf-1 free for the j=0 prefetch

    float O[16][4];
#pragma unroll
    for (int nf = 0; nf < 16; nf++)
#pragma unroll
        for (int cp = 0; cp < 4; cp++) O[nf][cp] = 0.f;
    float mold0 = -INFINITY, mold1 = -INFINITY, lp0 = 0.f, lp1 = 0.f;

    const int rk  = (qd >> 1) * 8 + l8;   // K B-frag row base (+16*nb)
    const int ckb = qd & 1;
    const int rv  = (qd & 1) * 8 + l8;    // V row base (+16*kc)
    const int cvq = qd >> 1;
    const int row0th = warp * 16 + g;     // thread's C rows: row0th, row0th+8

    for (int j = 0; j <= qt; j++) {
        const int buf = j & 1;
        const uint32_t Kb = sb + ATT_KOFF + buf * 16384;
        const uint32_t Vb = sb + ATT_VOFF + buf * 16384;

        // Prefetch tile j+1 into the other buffer (free since end of j-1).
        if (j < qt) {
            const __half* kn = kb + (size_t)(j + 1) * 64 * HSIZE;
            const __half* vn = vb + (size_t)(j + 1) * 64 * HSIZE;
            const uint32_t Knb = sb + ATT_KOFF + (buf ^ 1) * 16384;
            const uint32_t Vnb = sb + ATT_VOFF + (buf ^ 1) * 16384;
#pragma unroll
            for (int i = 0; i < 8; i++) {
                int lin = t + i * 128; int row = lin >> 4, ch = lin & 15;
                uint32_t dsw = (uint32_t)(row * 256 + ((ch ^ (row & 7)) << 4));
                CPA16(Knb + dsw, kn + row * 128 + ch * 8);
                CPA16(Vnb + dsw, vn + row * 128 + ch * 8);
            }
            CPA_COMMIT();
        }

        // ---- S = Q K^T : warp tile 16 x 64 ----
        float SC[8][4];
#pragma unroll
        for (int nf = 0; nf < 8; nf++)
#pragma unroll
            for (int cp = 0; cp < 4; cp++) SC[nf][cp] = 0.f;

#pragma unroll
        for (int ks = 0; ks < 8; ks++) {
            uint32_t bf[4];
#pragma unroll
            for (int nb = 0; nb < 4; nb++) {
                ldm4(bf, Kb + (16 * nb + rk) * 256 + (((2 * ks + ckb) ^ l8) << 4));
                mma16(SC[2 * nb],     Qf[ks], bf);
                mma16(SC[2 * nb + 1], Qf[ks], bf + 2);
            }
        }

        // Causal mask on the diagonal tile.
        if (j == qt) {
#pragma unroll
            for (int nf = 0; nf < 8; nf++) {
                int cc = 8 * nf + 2 * klo;
                if (cc     > row0th)     SC[nf][0] = -INFINITY;
                if (cc + 1 > row0th)     SC[nf][1] = -INFINITY;
                if (cc     > row0th + 8) SC[nf][2] = -INFINITY;
                if (cc + 1 > row0th + 8) SC[nf][3] = -INFINITY;
            }
        }

        // ---- warp-local softmax ----
        float m0 = -INFINITY, m1 = -INFINITY;
#pragma unroll
        for (int nf = 0; nf < 8; nf++) {
            m0 = fmaxf(m0, fmaxf(SC[nf][0], SC[nf][1]));
            m1 = fmaxf(m1, fmaxf(SC[nf][2], SC[nf][3]));
        }
        m0 = fmaxf(m0, __shfl_xor_sync(0xffffffffu, m0, 1));
        m0 = fmaxf(m0, __shfl_xor_sync(0xffffffffu, m0, 2));
        m1 = fmaxf(m1, __shfl_xor_sync(0xffffffffu, m1, 1));
        m1 = fmaxf(m1, __shfl_xor_sync(0xffffffffu, m1, 2));
        const float mn0 = fmaxf(mold0, m0), mn1 = fmaxf(mold1, m1);
        const float alpha0 = __expf(mold0 - mn0), alpha1 = __expf(mold1 - mn1);
        mold0 = mn0; mold1 = mn1;

        // exp -> fp16 (rounded once), accumulate l, repack into PV A-frags.
        uint32_t Pf[4][4];
        float s0 = 0.f, s1 = 0.f;
#pragma unroll
        for (int kc = 0; kc < 4; kc++) {
#pragma unroll
            for (int h = 0; h < 2; h++) {
                const int nf = 2 * kc + h;
                __half h0 = __float2half_rn(__expf(SC[nf][0] - mn0));
                __half h1 = __float2half_rn(__expf(SC[nf][1] - mn0));
                __half h2 = __float2half_rn(__expf(SC[nf][2] - mn1));
                __half h3 = __float2half_rn(__expf(SC[nf][3] - mn1));
                s0 += __half2float(h0) + __half2float(h1);
                s1 += __half2float(h2) + __half2float(h3);
                __half2 p01 = __halves2half2(h0, h1);
                __half2 p23 = __halves2half2(h2, h3);
                Pf[kc][0 + h * 2] = *reinterpret_cast<uint32_t*>(&p01);
                Pf[kc][1 + h * 2] = *reinterpret_cast<uint32_t*>(&p23);
            }
        }
        lp0 = lp0 * alpha0 + s0;
        lp1 = lp1 * alpha1 + s1;

        // Rescale O.
#pragma unroll
        for (int nf = 0; nf < 16; nf++) {
            O[nf][0] *= alpha0; O[nf][1] *= alpha0;
            O[nf][2] *= alpha1; O[nf][3] *= alpha1;
        }

        // ---- O += P V : warp tile 16 x 128, K = 64 ----
#pragma unroll
        for (int kc = 0; kc < 4; kc++) {
            uint32_t vf[4];
#pragma unroll
            for (int nv = 0; nv < 8; nv++) {
                ldm4t(vf, Vb + (16 * kc + rv) * 256 + (((2 * nv + cvq) ^ l8) << 4));
                mma16(O[2 * nv],     Pf[kc], vf);
                mma16(O[2 * nv + 1], Pf[kc], vf + 2);
            }
        }

        CPA_WAIT0();
        __syncthreads();   // tile j+1 visible; buffers recycled
    }

    // ---- epilogue: finish l across the quad, normalize, store ----
    lp0 += __shfl_xor_sync(0xffffffffu, lp0, 1);
    lp0 += __shfl_xor_sync(0xffffffffu, lp0, 2);
    lp1 += __shfl_xor_sync(0xffffffffu, lp1, 1);
    lp1 += __shfl_xor_sync(0xffffffffu, lp1, 2);
    const float inv0 = 1.f / lp0, inv1 = 1.f / lp1;

    float* op = out + (size_t)b * TSEQ * HSIZE;
    const int r0 = q0 + row0th, r1 = r0 + 8;
#pragma unroll
    for (int nf = 0; nf < 16; nf++) {
        const int cc = 8 * nf + 2 * klo;
        *reinterpret_cast<float2*>(op + (size_t)r0 * HSIZE + cc) =
            make_float2(O[nf][0] * inv0, O[nf][1] * inv0);
        *reinterpret_cast<float2*>(op + (size_t)r1 * HSIZE + cc) =
            make_float2(O[nf][2] * inv1, O[nf][3] * inv1);
    }
}

// ---------------------------------------------------------------------------
extern "C" void kernel_launch(void* const* d_in, const int* in_sizes, int n_in,
                              void* d_out, int out_size)
{
    const float* x  = (const float*)d_in[0];
    const float* Wq = (const float*)d_in[1];
    const float* Wk = (const float*)d_in[2];
    const float* Wv = (const float*)d_in[3];
    float* out = (float*)d_out;

    cudaFuncSetAttribute(qkv_kernel,
                         cudaFuncAttributeMaxDynamicSharedMemorySize, QKV_SMEM);
    qkv_kernel<<<dim3(3, NROWS / 128), 256, QKV_SMEM>>>(x, Wq, Wk, Wv);

    cudaFuncSetAttribute(attn_kernel,
                         cudaFuncAttributeMaxDynamicSharedMemorySize, ATT_SMEM);
    attn_kernel<<<256, 128, ATT_SMEM>>>(out);
}

// round 11
// speedup vs baseline: 1.1043x; 1.1043x over previous
#include <cuda_runtime.h>
#include <cuda_fp16.h>
#include <math.h>
#include <stdint.h>

#define NBATCH 4
#define TSEQ   4096
#define DMODEL 1024
#define HSIZE  128
#define NROWS  (NBATCH * TSEQ)

__device__ __align__(16) __half g_q[(size_t)NROWS * HSIZE];
__device__ __align__(16) __half g_k[(size_t)NROWS * HSIZE];
__device__ __align__(16) __half g_v[(size_t)NROWS * HSIZE];

// Split-KV partials: unnormalized O, row max m, row sum l, per split.
__device__ __align__(16) float g_op[2][(size_t)NROWS * HSIZE];
__device__ float g_mbuf[2][NROWS];
__device__ float g_lbuf[2][NROWS];

// ---------------------------------------------------------------------------
// Helpers
// ---------------------------------------------------------------------------
__device__ __forceinline__ uint32_t smem_u32(const void* p) {
    uint32_t a;
    asm("{ .reg .u64 t; cvta.to.shared.u64 t, %1; cvt.u32.u64 %0, t; }"
        : "=r"(a) : "l"(p));
    return a;
}

__device__ __forceinline__ uint32_t f2h2(float a, float b) {
    __half2 h = __floats2half2_rn(a, b);
    return *reinterpret_cast<uint32_t*>(&h);
}

__device__ __forceinline__ void mma16(float* c, const uint32_t* a, const uint32_t* b) {
    asm volatile(
        "mma.sync.aligned.m16n8k16.row.col.f32.f16.f16.f32 "
        "{%0,%1,%2,%3},{%4,%5,%6,%7},{%8,%9},{%0,%1,%2,%3};"
        : "+f"(c[0]), "+f"(c[1]), "+f"(c[2]), "+f"(c[3])
        : "r"(a[0]), "r"(a[1]), "r"(a[2]), "r"(a[3]), "r"(b[0]), "r"(b[1]));
}

__device__ __forceinline__ void ldm4(uint32_t* r, uint32_t a) {
    asm volatile("ldmatrix.sync.aligned.m8n8.x4.shared.b16 {%0,%1,%2,%3}, [%4];"
                 : "=r"(r[0]), "=r"(r[1]), "=r"(r[2]), "=r"(r[3]) : "r"(a));
}
__device__ __forceinline__ void ldm4t(uint32_t* r, uint32_t a) {
    asm volatile("ldmatrix.sync.aligned.m8n8.x4.trans.shared.b16 {%0,%1,%2,%3}, [%4];"
                 : "=r"(r[0]), "=r"(r[1]), "=r"(r[2]), "=r"(r[3]) : "r"(a));
}

#define CPA16(dst, src) \
    asm volatile("cp.async.cg.shared.global [%0], [%1], 16;" \
                 :: "r"(dst), "l"(src) : "memory")
#define CPA_COMMIT() asm volatile("cp.async.commit_group;" ::: "memory")
#define CPA_WAIT0()  asm volatile("cp.async.wait_group 0;" ::: "memory")

// ---------------------------------------------------------------------------
// Kernel 1: QKV projection, fp16 mma + ldmatrix, fp16 output (unchanged).
// Wq pre-scaled by 1/sqrt(128).
// ---------------------------------------------------------------------------
#define QKV_PITCH_B 80
#define QKV_TILE_B  (128 * QKV_PITCH_B)
#define QKV_STAGE_B (2 * QKV_TILE_B)
#define QKV_SMEM    (2 * QKV_STAGE_B)

__global__ __launch_bounds__(256, 1) void qkv_kernel(
    const float* __restrict__ x,
    const float* __restrict__ Wq,
    const float* __restrict__ Wk,
    const float* __restrict__ Wv)
{
    extern __shared__ char sm1[];
    const uint32_t sbase = smem_u32(sm1);

    const int w  = blockIdx.x;
    const int rb = blockIdx.y;
    const float* __restrict__ W = (w == 0) ? Wq : ((w == 1) ? Wk : Wv);
    __half* out = (w == 0) ? g_q : ((w == 1) ? g_k : g_v);
    const float ws = (w == 0) ? 0.08838834764831845f : 1.0f;
    const int row0 = rb * 128;

    const int t = threadIdx.x;
    const int warp = t >> 5, lane = t & 31;
    const int g = lane >> 2, klo = lane & 3;
    const int l8 = lane & 7, qd = lane >> 3;
    const int m0 = (warp >> 2) * 64;
    const int n0 = (warp & 3) * 32;

    uint32_t arow[4], brow[2];
#pragma unroll
    for (int mf = 0; mf < 4; mf++)
        arow[mf] = (uint32_t)((m0 + mf * 16 + (qd & 1) * 8 + l8) * QKV_PITCH_B
                              + (qd >> 1) * 16);
#pragma unroll
    for (int p = 0; p < 2; p++)
        brow[p] = (uint32_t)((n0 + p * 16 + (qd >> 1) * 8 + l8) * QKV_PITCH_B
                             + (qd & 1) * 16);

    float C[4][4][4];
#pragma unroll
    for (int a = 0; a < 4; a++)
#pragma unroll
        for (int bb = 0; bb < 4; bb++)
#pragma unroll
            for (int cp = 0; cp < 4; cp++) C[a][bb][cp] = 0.f;

    float4 ra[4], rbv[4];
    const int lr = t >> 3, lc = (t & 7) * 4;

#define QKV_LOADG(kt)                                                          \
    {                                                                          \
        int k0_ = (kt) * 32;                                                   \
        _Pragma("unroll")                                                      \
        for (int i = 0; i < 4; i++) {                                          \
            int r = lr + i * 32;                                               \
            ra[i]  = *reinterpret_cast<const float4*>(                         \
                x + (size_t)(row0 + r) * DMODEL + k0_ + lc);                   \
            rbv[i] = *reinterpret_cast<const float4*>(                         \
                W + (size_t)r * DMODEL + k0_ + lc);                            \
        }                                                                      \
    }

#define QKV_STS(buf)                                                           \
    {                                                                          \
        char* A_ = sm1 + (buf) * QKV_STAGE_B;                                  \
        char* B_ = A_ + QKV_TILE_B;                                            \
        _Pragma("unroll")                                                      \
        for (int i = 0; i < 4; i++) {                                          \
            int r = lr + i * 32;                                               \
            uint32_t bo = (uint32_t)(r * QKV_PITCH_B + lc * 2);                \
            *reinterpret_cast<uint2*>(A_ + bo) =                               \
                make_uint2(f2h2(ra[i].x, ra[i].y), f2h2(ra[i].z, ra[i].w));    \
            *reinterpret_cast<uint2*>(B_ + bo) =                               \
                make_uint2(f2h2(rbv[i].x * ws, rbv[i].y * ws),                 \
                           f2h2(rbv[i].z * ws, rbv[i].w * ws));                \
        }                                                                      \
    }

    QKV_LOADG(0);
    QKV_STS(0);
    QKV_LOADG(1);
    __syncthreads();

    for (int kt = 0; kt < 32; kt++) {
        const int cur = kt & 1;
        if (kt + 1 < 32) QKV_STS(cur ^ 1);
        if (kt + 2 < 32) QKV_LOADG(kt + 2);

        const uint32_t Ab = sbase + cur * QKV_STAGE_B;
        const uint32_t Bb = Ab + QKV_TILE_B;
#pragma unroll
        for (int ks = 0; ks < 2; ks++) {
            uint32_t af[4][4], bf[2][4];
#pragma unroll
            for (int mf = 0; mf < 4; mf++) ldm4(af[mf], Ab + arow[mf] + ks * 32);
#pragma unroll
            for (int p = 0; p < 2; p++)    ldm4(bf[p], Bb + brow[p] + ks * 32);
#pragma unroll
            for (int mf = 0; mf < 4; mf++) {
                mma16(C[mf][0], af[mf], bf[0]);
                mma16(C[mf][1], af[mf], bf[0] + 2);
                mma16(C[mf][2], af[mf], bf[1]);
                mma16(C[mf][3], af[mf], bf[1] + 2);
            }
        }
        __syncthreads();
    }

#pragma unroll
    for (int mf = 0; mf < 4; mf++)
#pragma unroll
        for (int nf = 0; nf < 4; nf++) {
            int r  = row0 + m0 + mf * 16 + g;
            int cc = n0 + nf * 8 + 2 * klo;
            *reinterpret_cast<__half2*>(out + (size_t)r * HSIZE + cc) =
                __floats2half2_rn(C[mf][nf][0], C[mf][nf][1]);
            *reinterpret_cast<__half2*>(out + (size_t)(r + 8) * HSIZE + cc) =
                __floats2half2_rn(C[mf][nf][2], C[mf][nf][3]);
        }
}

// ---------------------------------------------------------------------------
// Kernel 2: causal flash attention, FA2 warp-owned rows + split-KV.
// 512 CTAs: (batch, q-tile, split).  Split 0 -> KV tiles [0,h),
// split 1 -> [h, qt+1) incl. diagonal; h = (qt+1)>>1.
// Each split writes unnormalized O + (m, l); merge_kernel combines.
// ---------------------------------------------------------------------------
#define ATT_KOFF  0
#define ATT_VOFF  32768
#define ATT_SMEM  65536

__global__ __launch_bounds__(128, 3) void attn_kernel()
{
    extern __shared__ __align__(16) char smc[];
    const uint32_t sb = smem_u32(smc);

    // bid -> (split, batch, qt); heaviest chunks at low bid.
    const int bid = blockIdx.x;
    const int s   = bid & 1;
    const int r2  = bid >> 1;          // 0..255
    const int b   = r2 & 3;
    const int qt  = 63 - (r2 >> 2);
    const int q0  = qt * 64;
    const int h   = (qt + 1) >> 1;
    const int j0  = s ? h : 0;
    const int j1  = s ? (qt + 1) : h;

    const int t = threadIdx.x, warp = t >> 5, lane = t & 31;
    const int g = lane >> 2, klo = lane & 3;
    const int l8 = lane & 7, qd = lane >> 3;
    const int row0th = warp * 16 + g;

    const int gr0 = b * TSEQ + q0 + row0th;   // global row indices
    const int gr1 = gr0 + 8;

    if (j0 == j1) {   // empty split (qt==0, s==0): write zero partials
        for (int i = t; i < 64; i += 128) {
            g_mbuf[0][b * TSEQ + i] = -INFINITY;
            g_lbuf[0][b * TSEQ + i] = 0.f;
        }
        float4 z = make_float4(0.f, 0.f, 0.f, 0.f);
        for (int i = t; i < 64 * 32; i += 128)
            reinterpret_cast<float4*>(&g_op[0][(size_t)b * TSEQ * HSIZE])[i] = z;
        return;
    }

    const __half* qb = g_q + ((size_t)b * TSEQ + q0) * HSIZE;
    const __half* kb = g_k + (size_t)b * TSEQ * HSIZE;
    const __half* vb = g_v + (size_t)b * TSEQ * HSIZE;

    // Stage Q into K-buf-1; K/V tile j0 into buf 0.
    {
        const __half* k0p = kb + (size_t)j0 * 64 * HSIZE;
        const __half* v0p = vb + (size_t)j0 * 64 * HSIZE;
#pragma unroll
        for (int i = 0; i < 8; i++) {
            int lin = t + i * 128; int row = lin >> 4, ch = lin & 15;
            uint32_t dsw = (uint32_t)(row * 256 + ((ch ^ (row & 7)) << 4));
            CPA16(sb + ATT_KOFF + 16384 + dsw, qb + row * 128 + ch * 8);
            CPA16(sb + ATT_KOFF + dsw,         k0p + row * 128 + ch * 8);
            CPA16(sb + ATT_VOFF + dsw,         v0p + row * 128 + ch * 8);
        }
    }
    CPA_COMMIT();
    CPA_WAIT0();
    __syncthreads();

    // Hoist Q fragments to registers.
    uint32_t Qf[8][4];
    {
        const int rq = warp * 16 + (qd & 1) * 8 + l8;
        const int cqa = qd >> 1;
        const uint32_t Qb = sb + ATT_KOFF + 16384;
#pragma unroll
        for (int ks = 0; ks < 8; ks++)
            ldm4(Qf[ks], Qb + rq * 256 + (((2 * ks + cqa) ^ l8) << 4));
    }
    __syncthreads();   // K-buf-1 free for the first prefetch

    float O[16][4];
#pragma unroll
    for (int nf = 0; nf < 16; nf++)
#pragma unroll
        for (int cp = 0; cp < 4; cp++) O[nf][cp] = 0.f;
    float mold0 = -INFINITY, mold1 = -INFINITY, lp0 = 0.f, lp1 = 0.f;

    const int rk  = (qd >> 1) * 8 + l8;
    const int ckb = qd & 1;
    const int rv  = (qd & 1) * 8 + l8;
    const int cvq = qd >> 1;

    for (int j = j0; j < j1; j++) {
        const int buf = (j - j0) & 1;
        const uint32_t Kb = sb + ATT_KOFF + buf * 16384;
        const uint32_t Vb = sb + ATT_VOFF + buf * 16384;

        if (j + 1 < j1) {
            const __half* kn = kb + (size_t)(j + 1) * 64 * HSIZE;
            const __half* vn = vb + (size_t)(j + 1) * 64 * HSIZE;
            const uint32_t Knb = sb + ATT_KOFF + (buf ^ 1) * 16384;
            const uint32_t Vnb = sb + ATT_VOFF + (buf ^ 1) * 16384;
#pragma unroll
            for (int i = 0; i < 8; i++) {
                int lin = t + i * 128; int row = lin >> 4, ch = lin & 15;
                uint32_t dsw = (uint32_t)(row * 256 + ((ch ^ (row & 7)) << 4));
                CPA16(Knb + dsw, kn + row * 128 + ch * 8);
                CPA16(Vnb + dsw, vn + row * 128 + ch * 8);
            }
            CPA_COMMIT();
        }

        // ---- S = Q K^T : warp tile 16 x 64 ----
        float SC[8][4];
#pragma unroll
        for (int nf = 0; nf < 8; nf++)
#pragma unroll
            for (int cp = 0; cp < 4; cp++) SC[nf][cp] = 0.f;

#pragma unroll
        for (int ks = 0; ks < 8; ks++) {
            uint32_t bf[4];
#pragma unroll
            for (int nb = 0; nb < 4; nb++) {
                ldm4(bf, Kb + (16 * nb + rk) * 256 + (((2 * ks + ckb) ^ l8) << 4));
                mma16(SC[2 * nb],     Qf[ks], bf);
                mma16(SC[2 * nb + 1], Qf[ks], bf + 2);
            }
        }

        // Causal mask (only split 1's final tile is the diagonal).
        if (j == qt) {
#pragma unroll
            for (int nf = 0; nf < 8; nf++) {
                int cc = 8 * nf + 2 * klo;
                if (cc     > row0th)     SC[nf][0] = -INFINITY;
                if (cc + 1 > row0th)     SC[nf][1] = -INFINITY;
                if (cc     > row0th + 8) SC[nf][2] = -INFINITY;
                if (cc + 1 > row0th + 8) SC[nf][3] = -INFINITY;
            }
        }

        // ---- warp-local softmax ----
        float m0 = -INFINITY, m1 = -INFINITY;
#pragma unroll
        for (int nf = 0; nf < 8; nf++) {
            m0 = fmaxf(m0, fmaxf(SC[nf][0], SC[nf][1]));
            m1 = fmaxf(m1, fmaxf(SC[nf][2], SC[nf][3]));
        }
        m0 = fmaxf(m0, __shfl_xor_sync(0xffffffffu, m0, 1));
        m0 = fmaxf(m0, __shfl_xor_sync(0xffffffffu, m0, 2));
        m1 = fmaxf(m1, __shfl_xor_sync(0xffffffffu, m1, 1));
        m1 = fmaxf(m1, __shfl_xor_sync(0xffffffffu, m1, 2));
        const float mn0 = fmaxf(mold0, m0), mn1 = fmaxf(mold1, m1);
        const float alpha0 = __expf(mold0 - mn0), alpha1 = __expf(mold1 - mn1);
        mold0 = mn0; mold1 = mn1;

        // exp -> fp16 (rounded once), accumulate l, repack into PV A-frags.
        uint32_t Pf[4][4];
        float s0 = 0.f, s1 = 0.f;
#pragma unroll
        for (int kc = 0; kc < 4; kc++) {
#pragma unroll
            for (int hh = 0; hh < 2; hh++) {
                const int nf = 2 * kc + hh;
                __half h0 = __float2half_rn(__expf(SC[nf][0] - mn0));
                __half h1 = __float2half_rn(__expf(SC[nf][1] - mn0));
                __half h2 = __float2half_rn(__expf(SC[nf][2] - mn1));
                __half h3 = __float2half_rn(__expf(SC[nf][3] - mn1));
                s0 += __half2float(h0) + __half2float(h1);
                s1 += __half2float(h2) + __half2float(h3);
                __half2 p01 = __halves2half2(h0, h1);
                __half2 p23 = __halves2half2(h2, h3);
                Pf[kc][0 + hh * 2] = *reinterpret_cast<uint32_t*>(&p01);
                Pf[kc][1 + hh * 2] = *reinterpret_cast<uint32_t*>(&p23);
            }
        }
        lp0 = lp0 * alpha0 + s0;
        lp1 = lp1 * alpha1 + s1;

#pragma unroll
        for (int nf = 0; nf < 16; nf++) {
            O[nf][0] *= alpha0; O[nf][1] *= alpha0;
            O[nf][2] *= alpha1; O[nf][3] *= alpha1;
        }

        // ---- O += P V : warp tile 16 x 128, K = 64 ----
#pragma unroll
        for (int kc = 0; kc < 4; kc++) {
            uint32_t vf[4];
#pragma unroll
            for (int nv = 0; nv < 8; nv++) {
                ldm4t(vf, Vb + (16 * kc + rv) * 256 + (((2 * nv + cvq) ^ l8) << 4));
                mma16(O[2 * nv],     Pf[kc], vf);
                mma16(O[2 * nv + 1], Pf[kc], vf + 2);
            }
        }

        CPA_WAIT0();
        __syncthreads();
    }

    // ---- epilogue: finish l across the quad, store UNNORMALIZED partials ----
    lp0 += __shfl_xor_sync(0xffffffffu, lp0, 1);
    lp0 += __shfl_xor_sync(0xffffffffu, lp0, 2);
    lp1 += __shfl_xor_sync(0xffffffffu, lp1, 1);
    lp1 += __shfl_xor_sync(0xffffffffu, lp1, 2);

    float* op = g_op[s];
#pragma unroll
    for (int nf = 0; nf < 16; nf++) {
        const int cc = 8 * nf + 2 * klo;
        *reinterpret_cast<float2*>(op + (size_t)gr0 * HSIZE + cc) =
            make_float2(O[nf][0], O[nf][1]);
        *reinterpret_cast<float2*>(op + (size_t)gr1 * HSIZE + cc) =
            make_float2(O[nf][2], O[nf][3]);
    }
    if (klo == 0) {
        g_mbuf[s][gr0] = mold0; g_lbuf[s][gr0] = lp0;
        g_mbuf[s][gr1] = mold1; g_lbuf[s][gr1] = lp1;
    }
}

// ---------------------------------------------------------------------------
// Kernel 3: merge the two splits per row (log-sum-exp weighted).
// 524288 float4s; grid 2048 x 256.
// ---------------------------------------------------------------------------
__global__ __launch_bounds__(256) void merge_kernel(float* __restrict__ out)
{
    const int gid = blockIdx.x * 256 + threadIdx.x;
    const int row = gid >> 5;
    const int c4  = (gid & 31) * 4;

    const float m0 = g_mbuf[0][row], m1 = g_mbuf[1][row];
    const float l0 = g_lbuf[0][row], l1 = g_lbuf[1][row];
    const float m  = fmaxf(m0, m1);
    const float w0 = __expf(m0 - m), w1 = __expf(m1 - m);
    const float inv = 1.f / (w0 * l0 + w1 * l1);

    const float4 a = *reinterpret_cast<const float4*>(
        &g_op[0][(size_t)row * HSIZE + c4]);
    const float4 c = *reinterpret_cast<const float4*>(
        &g_op[1][(size_t)row * HSIZE + c4]);
    *reinterpret_cast<float4*>(out + (size_t)row * HSIZE + c4) =
        make_float4((w0 * a.x + w1 * c.x) * inv, (w0 * a.y + w1 * c.y) * inv,
                    (w0 * a.z + w1 * c.z) * inv, (w0 * a.w + w1 * c.w) * inv);
}

// ---------------------------------------------------------------------------
extern "C" void kernel_launch(void* const* d_in, const int* in_sizes, int n_in,
                              void* d_out, int out_size)
{
    const float* x  = (const float*)d_in[0];
    const float* Wq = (const float*)d_in[1];
    const float* Wk = (const float*)d_in[2];
    const float* Wv = (const float*)d_in[3];
    float* out = (float*)d_out;

    cudaFuncSetAttribute(qkv_kernel,
                         cudaFuncAttributeMaxDynamicSharedMemorySize, QKV_SMEM);
    qkv_kernel<<<dim3(3, NROWS / 128), 256, QKV_SMEM>>>(x, Wq, Wk, Wv);

    cudaFuncSetAttribute(attn_kernel,
                         cudaFuncAttributeMaxDynamicSharedMemorySize, ATT_SMEM);
    attn_kernel<<<512, 128, ATT_SMEM>>>();

    merge_kernel<<<NROWS * HSIZE / 4 / 256, 256>>>(out);
}